// round 5
// baseline (speedup 1.0000x reference)
#include <cuda_runtime.h>
#include <math.h>
#include <stdint.h>

#define B_SZ 2
#define L 1024
#define D 384
#define PATCH_DIM 4096
#define DEPTH 12
#define DSTATE 16
#define DTRANK 24
#define DBL_N 56
#define NTOK (B_SZ * L)   // 2048
#define NCH 8             // scan chunks
#define CHL (L / NCH)     // 128 steps per chunk

typedef unsigned long long ull;

// ------------------------- scratch (static device) -------------------------
__device__ float g_tok[NTOK * D];
__device__ float g_h[NTOK * D];
__device__ float g_xz[NTOK * 2 * D];
__device__ float g_xc[NTOK * D];
__device__ float g_dbl[NTOK * DBL_N];
__device__ float g_y[NTOK * D];

// ------------------------- cp.async + f32x2 helpers ------------------------
__device__ __forceinline__ void cp_async16(uint32_t dst, const void* src, bool pred) {
    int sz = pred ? 16 : 0;
    asm volatile("cp.async.ca.shared.global [%0], [%1], 16, %2;\n"
                 :: "r"(dst), "l"(src), "r"(sz));
}
__device__ __forceinline__ void cp_commit() {
    asm volatile("cp.async.commit_group;\n");
}
template <int N>
__device__ __forceinline__ void cp_wait() {
    asm volatile("cp.async.wait_group %0;\n" :: "n"(N));
}
__device__ __forceinline__ ull pack2(float x, float y) {
    ull r; asm("mov.b64 %0, {%1, %2};" : "=l"(r) : "f"(x), "f"(y)); return r;
}
__device__ __forceinline__ void unpack2(ull v, float& x, float& y) {
    asm("mov.b64 {%0, %1}, %2;" : "=f"(x), "=f"(y) : "l"(v));
}
__device__ __forceinline__ void ffma2(ull& d, ull a, ull b) {
    asm("fma.rn.f32x2 %0, %1, %2, %0;" : "+l"(d) : "l"(a), "l"(b));
}

// ------------------------- pipelined SGEMM 64x64 (FFMA2) -------------------
#define BM 64
#define BN 64
#define BK 16
#define ASTRIDE 20

struct SmemGemm {
    __align__(16) float As[2][BM * ASTRIDE];
    __align__(16) float Bs[2][BK * BN];
};

// epi: 0 none, 1 +bias, 3 C += result. gridDim.z>1 -> split-K atomicAdd.
__global__ void sgemm_k(const float* __restrict__ A, int lda,
                        const float* __restrict__ Bm,
                        float* __restrict__ C,
                        const float* __restrict__ bias,
                        int M, int N, int K, int epi)
{
    __shared__ SmemGemm sm;
    const int bm = blockIdx.y * BM, bn = blockIdx.x * BN;
    const int tid = threadIdx.x;

    const int ksplit = gridDim.z;
    const int kc = K / ksplit;
    const int kstart = blockIdx.z * kc;
    const int kend = kstart + kc;
    const int niters = (kc + BK - 1) / BK;

    const int am  = tid >> 2;
    const int akq = (tid & 3) << 2;
    const int bkb = tid >> 4;
    const int bn4 = (tid & 15) << 2;
    const bool bn_ok = (bn + bn4) < N;

    const float* Arow = A + (size_t)(bm + am) * lda;

    uint32_t sAs = (uint32_t)__cvta_generic_to_shared(&sm.As[0][0]);
    uint32_t sBs = (uint32_t)__cvta_generic_to_shared(&sm.Bs[0][0]);

    auto load_stage = [&](int it, int buf) {
        int k0 = kstart + it * BK;
        {
            int k = k0 + akq;
            bool p = k < kend;
            const float* src = p ? (Arow + k) : A;
            cp_async16(sAs + (buf * BM * ASTRIDE + am * ASTRIDE + akq) * 4, src, p);
        }
        {
            int k = k0 + bkb;
            bool p = (k < kend) && bn_ok;
            const float* src = p ? (Bm + (size_t)k * N + bn + bn4) : Bm;
            cp_async16(sBs + (buf * BK * BN + bkb * BN + bn4) * 4, src, p);
        }
    };

    const int ty = tid >> 4, tx = tid & 15;
    const int m0 = ty * 4, n0 = tx * 4;

    ull acc2[4][2];
    #pragma unroll
    for (int i = 0; i < 4; i++) { acc2[i][0] = 0ull; acc2[i][1] = 0ull; }

    load_stage(0, 0); cp_commit();
    if (niters > 1) load_stage(1, 1);
    cp_commit();

    for (int it = 0; it < niters; it++) {
        cp_wait<1>();
        __syncthreads();
        const int buf = it & 1;
        const float* As = &sm.As[buf][0];
        const float* Bsr = &sm.Bs[buf][0];
        #pragma unroll
        for (int kk = 0; kk < BK; kk++) {
            float a0 = As[(m0 + 0) * ASTRIDE + kk];
            float a1 = As[(m0 + 1) * ASTRIDE + kk];
            float a2 = As[(m0 + 2) * ASTRIDE + kk];
            float a3 = As[(m0 + 3) * ASTRIDE + kk];
            ull b01 = *reinterpret_cast<const ull*>(&Bsr[kk * BN + n0]);
            ull b23 = *reinterpret_cast<const ull*>(&Bsr[kk * BN + n0 + 2]);
            ull ap;
            ap = pack2(a0, a0); ffma2(acc2[0][0], ap, b01); ffma2(acc2[0][1], ap, b23);
            ap = pack2(a1, a1); ffma2(acc2[1][0], ap, b01); ffma2(acc2[1][1], ap, b23);
            ap = pack2(a2, a2); ffma2(acc2[2][0], ap, b01); ffma2(acc2[2][1], ap, b23);
            ap = pack2(a3, a3); ffma2(acc2[3][0], ap, b01); ffma2(acc2[3][1], ap, b23);
        }
        __syncthreads();
        if (it + 2 < niters) load_stage(it + 2, buf);
        cp_commit();
    }

    #pragma unroll
    for (int i = 0; i < 4; i++) {
        int row = bm + m0 + i;
        float v[4];
        unpack2(acc2[i][0], v[0], v[1]);
        unpack2(acc2[i][1], v[2], v[3]);
        #pragma unroll
        for (int j = 0; j < 4; j++) {
            int col = bn + n0 + j;
            if (col < N) {
                size_t off = (size_t)row * N + col;
                float vv = v[j];
                if (ksplit > 1) {
                    atomicAdd(&C[off], vv);
                } else {
                    if (epi == 1) vv += bias[col];
                    if (epi == 3) vv += C[off];
                    C[off] = vv;
                }
            }
        }
    }
}

// ------------------------- patchify GEMM (im2col fused, FFMA2) -------------
__global__ void sgemm_patch_k(const float* __restrict__ X,
                              const float* __restrict__ Bm,
                              float* __restrict__ C,
                              const float* __restrict__ bias)
{
    __shared__ SmemGemm sm;
    const int bm = blockIdx.y * BM, bn = blockIdx.x * BN;
    const int tid = threadIdx.x;
    const int N = D, K = PATCH_DIM;
    const int niters = K / BK;

    const int am  = tid >> 2;
    const int akq = (tid & 3) << 2;
    const int bkb = tid >> 4;
    const int bn4 = (tid & 15) << 2;

    const int m = bm + am;
    const int b = m >> 10, l = m & 1023;
    const int gh = l >> 6, gw = (l >> 3) & 7, gd = l & 7;
    const size_t xbase = ((size_t)(b * 256 + gh * 16) * 256 + gw * 32) * 64 + gd * 8;

    uint32_t sAs = (uint32_t)__cvta_generic_to_shared(&sm.As[0][0]);
    uint32_t sBs = (uint32_t)__cvta_generic_to_shared(&sm.Bs[0][0]);

    auto load_stage = [&](int it, int buf) {
        int k0 = it * BK;
        {
            int k = k0 + akq;
            int ph = k >> 8, pw = (k >> 3) & 31, pd = k & 7;
            const float* src = X + xbase + (size_t)ph * 16384 + pw * 64 + pd;
            cp_async16(sAs + (buf * BM * ASTRIDE + am * ASTRIDE + akq) * 4, src, true);
        }
        {
            int k = k0 + bkb;
            const float* src = Bm + (size_t)k * N + bn + bn4;
            cp_async16(sBs + (buf * BK * BN + bkb * BN + bn4) * 4, src, true);
        }
    };

    const int ty = tid >> 4, tx = tid & 15;
    const int m0 = ty * 4, n0 = tx * 4;

    ull acc2[4][2];
    #pragma unroll
    for (int i = 0; i < 4; i++) { acc2[i][0] = 0ull; acc2[i][1] = 0ull; }

    load_stage(0, 0); cp_commit();
    load_stage(1, 1); cp_commit();

    for (int it = 0; it < niters; it++) {
        cp_wait<1>();
        __syncthreads();
        const int buf = it & 1;
        const float* As = &sm.As[buf][0];
        const float* Bsr = &sm.Bs[buf][0];
        #pragma unroll
        for (int kk = 0; kk < BK; kk++) {
            float a0 = As[(m0 + 0) * ASTRIDE + kk];
            float a1 = As[(m0 + 1) * ASTRIDE + kk];
            float a2 = As[(m0 + 2) * ASTRIDE + kk];
            float a3 = As[(m0 + 3) * ASTRIDE + kk];
            ull b01 = *reinterpret_cast<const ull*>(&Bsr[kk * BN + n0]);
            ull b23 = *reinterpret_cast<const ull*>(&Bsr[kk * BN + n0 + 2]);
            ull ap;
            ap = pack2(a0, a0); ffma2(acc2[0][0], ap, b01); ffma2(acc2[0][1], ap, b23);
            ap = pack2(a1, a1); ffma2(acc2[1][0], ap, b01); ffma2(acc2[1][1], ap, b23);
            ap = pack2(a2, a2); ffma2(acc2[2][0], ap, b01); ffma2(acc2[2][1], ap, b23);
            ap = pack2(a3, a3); ffma2(acc2[3][0], ap, b01); ffma2(acc2[3][1], ap, b23);
        }
        __syncthreads();
        if (it + 2 < niters) load_stage(it + 2, buf);
        cp_commit();
    }

    #pragma unroll
    for (int i = 0; i < 4; i++) {
        int row = bm + m0 + i;
        float v[4];
        unpack2(acc2[i][0], v[0], v[1]);
        unpack2(acc2[i][1], v[2], v[3]);
        #pragma unroll
        for (int j = 0; j < 4; j++) {
            int col = bn + n0 + j;
            C[(size_t)row * N + col] = v[j] + bias[col];
        }
    }
}

// ------------------------- LayerNorm (row of 384) + dbl zeroing ------------
__global__ void ln_k(const float* __restrict__ in, float* __restrict__ out,
                     const float* __restrict__ w, const float* __restrict__ b,
                     float* __restrict__ zbuf)
{
    int row = blockIdx.x;
    int t = threadIdx.x;   // 128 threads
    if (zbuf != nullptr && t < DBL_N) zbuf[(size_t)row * DBL_N + t] = 0.f;
    const float* r = in + (size_t)row * D;
    float v0 = r[t], v1 = r[t + 128], v2 = r[t + 256];
    float s = v0 + v1 + v2;
    __shared__ float sh[4], sh2[4];
    #pragma unroll
    for (int o = 16; o; o >>= 1) s += __shfl_xor_sync(~0u, s, o);
    if ((t & 31) == 0) sh[t >> 5] = s;
    __syncthreads();
    float mu = (sh[0] + sh[1] + sh[2] + sh[3]) * (1.f / 384.f);
    float d0 = v0 - mu, d1 = v1 - mu, d2 = v2 - mu;
    float q = d0 * d0 + d1 * d1 + d2 * d2;
    #pragma unroll
    for (int o = 16; o; o >>= 1) q += __shfl_xor_sync(~0u, q, o);
    if ((t & 31) == 0) sh2[t >> 5] = q;
    __syncthreads();
    float var = (sh2[0] + sh2[1] + sh2[2] + sh2[3]) * (1.f / 384.f);
    float rs = rsqrtf(var + 1e-5f);
    float* o = out + (size_t)row * D;
    o[t]       = d0 * rs * w[t]       + b[t];
    o[t + 128] = d1 * rs * w[t + 128] + b[t + 128];
    o[t + 256] = d2 * rs * w[t + 256] + b[t + 256];
}

// ------------------------- positional embedding ----------------------------
__global__ void posembed_k(const float* __restrict__ bp,
                           const unsigned char* __restrict__ mask)
{
    int row = blockIdx.x;           // NTOK
    int d = threadIdx.x;            // 384
    int b = row >> 10, l = row & 1023;
    int gh = l >> 6, gw = (l >> 3) & 7, gd = l & 7;
    float vr = bp[b * 4 + 2];
    bool m = mask[b] != 0;
    int j = d / 128, r = d - j * 128, f = r & 63;
    float c;
    if (j == 0)      c = (float)gh * (1.f / 15.f);
    else if (j == 1) c = ((float)gw - 4.f) * 0.25f;
    else {
        float v = m ? ((float)gd - 4.f) * vr : (float)gd * vr;
        float den = m ? 4.f * vr : 7.f * vr;
        c = v / den;
    }
    float omega = powf(10000.f, -(float)f * (1.f / 64.f));
    float ph = c * omega;
    g_tok[(size_t)row * D + d] += (r < 64) ? sinf(ph) : cosf(ph);
}

// ------------------------- causal depthwise conv + silu --------------------
__global__ void conv_k(const float* __restrict__ cw, const float* __restrict__ cb)
{
    int row = blockIdx.x;           // NTOK
    int d = threadIdx.x;            // 384
    int l = row & 1023, b = row >> 10;
    float acc = cb[d];
    #pragma unroll
    for (int j = 0; j < 4; j++) {
        int ll = l - 3 + j;
        if (ll >= 0)
            acc = fmaf(g_xz[(size_t)((b << 10) + ll) * (2 * D) + d], cw[d * 4 + j], acc);
    }
    g_xc[(size_t)row * D + d] = acc / (1.f + __expf(-acc));
}

// ------------------------- fused chunked selective scan --------------------
// One block (128 threads) per chain (b, d). Grid = 768 blocks.
// Phase A: compute dt = softplus(dbl[:, :24] @ dtw[:, d] + dtb[d]) for all
//          L tokens + stash xc into smem (dt_proj GEMM eliminated).
// Phase B: 8 units (16 lanes each) scan their 128-step chunk with h0 = 0,
//          producing (P = prod dA, W = end state).
// Phase C: in-block prefix fold.
// Phase D: replay chunk with true h0, emit y.
__global__ void scan_k(const float* __restrict__ A_log,
                       const float* __restrict__ dtw,
                       const float* __restrict__ dtb,
                       const float* __restrict__ Dsk)
{
    __shared__ float s_dt[L];
    __shared__ float s_xc[L];
    __shared__ float s_P[NCH][DSTATE];
    __shared__ float s_W[NCH][DSTATE];

    const int tid = threadIdx.x;    // 128
    const int blk = blockIdx.x;     // 0..767
    const int b = blk / D;
    const int d = blk - b * D;

    // ---- phase A: dt + xc stash ----
    float wreg[DTRANK];
    #pragma unroll
    for (int r = 0; r < DTRANK; r++) wreg[r] = __ldg(&dtw[r * D + d]);
    const float bias = __ldg(&dtb[d]);
    const float* dbl_b = g_dbl + (size_t)b * L * DBL_N;
    const float* xc_g  = g_xc + (size_t)b * L * D + d;

    #pragma unroll
    for (int i = 0; i < L / 128; i++) {
        int l = tid + i * 128;
        const float* row = dbl_b + (size_t)l * DBL_N;
        float acc = bias;
        #pragma unroll
        for (int r = 0; r < DTRANK; r++) acc = fmaf(__ldg(row + r), wreg[r], acc);
        s_dt[l] = (acc > 20.f) ? acc : log1pf(__expf(acc));
        s_xc[l] = __ldg(xc_g + (size_t)l * D);
    }
    __syncthreads();

    // ---- phase B: per-chunk local scan ----
    const int u = tid >> 4, lane = tid & 15;
    const float Aa = -__expf(A_log[d * DSTATE + lane]);
    const float* B_g = dbl_b + DTRANK + lane;
    const int l0 = u * CHL;

    float h = 0.f, P = 1.f;
    #pragma unroll 4
    for (int l = 0; l < CHL; l++) {
        float dtv = s_dt[l0 + l];
        float uv  = s_xc[l0 + l];
        float Bv  = __ldg(B_g + (size_t)(l0 + l) * DBL_N);
        float dA  = __expf(dtv * Aa);
        h = fmaf(h, dA, dtv * uv * Bv);
        P *= dA;
    }
    s_P[u][lane] = P;
    s_W[u][lane] = h;
    __syncthreads();

    // ---- phase C: prefix fold ----
    h = 0.f;
    for (int j = 0; j < u; j++)
        h = fmaf(h, s_P[j][lane], s_W[j][lane]);

    // ---- phase D: replay with output ----
    const float Dp = __ldg(&Dsk[d]);
    const float* z_g = g_xz + (size_t)b * L * (2 * D) + D + d;
    float* y_g = g_y + (size_t)b * L * D + d;

    #pragma unroll 4
    for (int l = 0; l < CHL; l++) {
        int ll = l0 + l;
        float dtv = s_dt[ll];
        float uv  = s_xc[ll];
        float Bv  = __ldg(B_g + (size_t)ll * DBL_N);
        float Cv  = __ldg(B_g + (size_t)ll * DBL_N + DSTATE);
        float dA  = __expf(dtv * Aa);
        h = fmaf(h, dA, dtv * uv * Bv);
        float p = h * Cv;
        p += __shfl_xor_sync(0xffffffffu, p, 8);
        p += __shfl_xor_sync(0xffffffffu, p, 4);
        p += __shfl_xor_sync(0xffffffffu, p, 2);
        p += __shfl_xor_sync(0xffffffffu, p, 1);
        if (lane == 0) {
            float zv = __ldg(z_g + (size_t)ll * 2 * D);
            float sz = zv / (1.f + __expf(-zv));
            y_g[(size_t)ll * D] = (p + uv * Dp) * sz;
        }
    }
}

// ------------------------- launch ------------------------------------------
extern "C" void kernel_launch(void* const* d_in, const int* in_sizes, int n_in,
                              void* d_out, int out_size)
{
    const float* x          = (const float*)d_in[0];
    const float* bp         = (const float*)d_in[1];
    const float* patch_w    = (const float*)d_in[2];
    const float* patch_b    = (const float*)d_in[3];
    const float* in_proj_w  = (const float*)d_in[4];
    const float* conv_w     = (const float*)d_in[5];
    const float* conv_b     = (const float*)d_in[6];
    const float* x_proj_w   = (const float*)d_in[7];
    const float* dt_proj_w  = (const float*)d_in[8];
    const float* dt_proj_b  = (const float*)d_in[9];
    const float* A_log      = (const float*)d_in[10];
    const float* Dskip      = (const float*)d_in[11];
    const float* out_proj_w = (const float*)d_in[12];
    const float* norm_w     = (const float*)d_in[13];
    const float* norm_b     = (const float*)d_in[14];
    const float* fw         = (const float*)d_in[15];
    const float* fb         = (const float*)d_in[16];
    const unsigned char* mask = (const unsigned char*)d_in[17];

    float *tok, *h, *xz, *xc, *dbl, *y;
    cudaGetSymbolAddress((void**)&tok, g_tok);
    cudaGetSymbolAddress((void**)&h,   g_h);
    cudaGetSymbolAddress((void**)&xz,  g_xz);
    cudaGetSymbolAddress((void**)&xc,  g_xc);
    cudaGetSymbolAddress((void**)&dbl, g_dbl);
    cudaGetSymbolAddress((void**)&y,   g_y);

    sgemm_patch_k<<<dim3(D / 64, NTOK / 64), 256>>>(x, patch_w, tok, patch_b);
    posembed_k<<<NTOK, D>>>(bp, mask);

    for (int layer = 0; layer < DEPTH; layer++) {
        ln_k<<<NTOK, 128>>>(tok, h, norm_w + layer * D, norm_b + layer * D, dbl);
        sgemm_k<<<dim3((2 * D) / 64, NTOK / 64, 1), 256>>>(h, D,
                in_proj_w + (size_t)layer * D * 2 * D, xz, nullptr, NTOK, 2 * D, D, 0);
        conv_k<<<NTOK, D>>>(conv_w + (size_t)layer * D * 4, conv_b + (size_t)layer * D);
        sgemm_k<<<dim3(1, NTOK / 64, 4), 256>>>(xc, D,
                x_proj_w + (size_t)layer * D * DBL_N, dbl, nullptr, NTOK, DBL_N, D, 0);
        scan_k<<<B_SZ * D, 128>>>(A_log + (size_t)layer * D * DSTATE,
                                  dt_proj_w + (size_t)layer * DTRANK * D,
                                  dt_proj_b + (size_t)layer * D,
                                  Dskip + (size_t)layer * D);
        sgemm_k<<<dim3(D / 64, NTOK / 64, 1), 256>>>(y, D,
                out_proj_w + (size_t)layer * D * D, tok, nullptr, NTOK, D, D, 3);
    }

    ln_k<<<NTOK, 128>>>(tok, (float*)d_out, fw, fb, nullptr);
}